// round 12
// baseline (speedup 1.0000x reference)
#include <cuda_runtime.h>
#include <cstdint>

// ImprovedVectorizationLoss: fused masked-L1 + BCE + continuity + recon-MSE.
// Persistent work-stealing kernel (740 blocks, 5/SM) with a tile-granular
// cp.async ring pipeline: each 256-record tile buffer is refilled for the
// NEXT segment immediately after its compute frees it, giving every prefetch
// a full tile-compute of latency coverage.

#define M_ROW 4096
#define TPB   256
#define SEGS  8
#define SEG   (M_ROW / SEGS)         // 512
#define TILE  256
#define NF4T  (TILE * 9 / 4)         // 576 float4 per tile per tensor
#define NBLOCKS 740                  // 5 blocks/SM x 148 SMs, single wave
#define BMAX  512
#define EPSV  1e-7f

__device__ float        g_acc[6];                  // [coord,width,bce,nvalid,cont,recon]
__device__ unsigned int g_ticket;
__device__ unsigned int g_work;                    // segment work counter
__device__ int          g_first_idx[BMAX * SEGS];
__device__ float2       g_first_p45[BMAX * SEGS];
__device__ float2       g_last_p45[BMAX * SEGS];

__device__ __forceinline__ float warpReduceSumF(float v) {
#pragma unroll
    for (int o = 16; o > 0; o >>= 1) v += __shfl_down_sync(0xffffffffu, v, o);
    return v;
}

__device__ __forceinline__ void cp16(void* s, const void* g) {
    unsigned saddr = (unsigned)__cvta_generic_to_shared(s);
    asm volatile("cp.async.cg.shared.global [%0], [%1], 16;" :: "r"(saddr), "l"(g));
}
#define CP_COMMIT() asm volatile("cp.async.commit_group;")
#define CP_WAIT(n)  asm volatile("cp.async.wait_group %0;" :: "n"(n))

__global__ __launch_bounds__(TPB, 5) void loss_fused_kernel(
    const float* __restrict__ preds, const float* __restrict__ tgts,
    const float* __restrict__ rec,   const float* __restrict__ img,
    float* __restrict__ out, int B, int nrec)
{
    __shared__ float    sp[2][TILE * 9];   // 18 KB (tile ring, predictions)
    __shared__ float    st[2][TILE * 9];   // 18 KB (tile ring, targets)
    __shared__ float2   s45f[SEG];         // 4 KB
    __shared__ unsigned smask[16];
    __shared__ float    swred[6][8];
    __shared__ int      s_seg;             // next stolen segment
    __shared__ int      slast;

    const int tid  = threadIdx.x;
    const int bid  = blockIdx.x;
    const int lane = tid & 31;
    const int wid  = tid >> 5;
    const int NSEG = B * SEGS;

    float coordS = 0.f, widthS = 0.f, bceS = 0.f, nvS = 0.f, contS = 0.f, reconS = 0.f;

    // ---- prologue: steal first segment, prefetch both of its tiles ----
    if (tid == 0) s_seg = (int)atomicAdd(&g_work, 1u);
    __syncthreads();
    int seg = s_seg;

    if (seg < NSEG) {
#pragma unroll
        for (int tl = 0; tl < 2; tl++) {
            const float4* p4 = reinterpret_cast<const float4*>(preds + ((size_t)seg * SEG + tl * TILE) * 9);
            const float4* t4 = reinterpret_cast<const float4*>(tgts  + ((size_t)seg * SEG + tl * TILE) * 9);
            float4* spd = reinterpret_cast<float4*>(&sp[tl][0]);
            float4* std_ = reinterpret_cast<float4*>(&st[tl][0]);
            for (int i = tid; i < NF4T; i += TPB) {
                cp16(&spd[i], &p4[i]);
                cp16(&std_[i], &t4[i]);
            }
            CP_COMMIT();
        }
    }

    // ---- recon MSE burst overlaps the first prefetch ----
    {
        const float4* r4 = reinterpret_cast<const float4*>(rec);
        const float4* i4 = reinterpret_cast<const float4*>(img);
        const int n4 = nrec >> 2;
        for (int i = bid * TPB + tid; i < n4; i += NBLOCKS * TPB) {
            float4 r = r4[i], m = i4[i];
            float dx = r.x - m.x, dy = r.y - m.y, dz = r.z - m.z, dw = r.w - m.w;
            reconS += dx * dx + dy * dy + dz * dz + dw * dw;
        }
    }

    // ---- persistent segment loop, tile-ring pipelined ----
    while (seg < NSEG) {
        if (tid == 0) s_seg = (int)atomicAdd(&g_work, 1u);   // steal next early

        // ======== TILE 0 ========
        CP_WAIT(1);            // buf0's group done (buf1's may still fly)
        __syncthreads();       // data visible; also publishes s_seg
        const int segn = s_seg;

        unsigned v0, v1;
        float2   q45[2];
        {
            const float* pr = &sp[0][tid * 9];
            const float* tr = &st[0][tid * 9];
            float t8   = tr[8];
            float mask = (t8 > 0.5f) ? 1.0f : 0.0f;
            v0 = (t8 > 0.5f) ? 1u : 0u;

            float a4 = pr[4], a5 = pr[5];
            coordS += (fabsf(pr[0] - tr[0]) + fabsf(pr[1] - tr[1]) + fabsf(pr[2] - tr[2])
                     + fabsf(pr[3] - tr[3]) + fabsf(a4 - tr[4]) + fabsf(a5 - tr[5])) * mask;
            widthS += (fabsf(pr[6] - tr[6]) + fabsf(pr[7] - tr[7])) * mask;
            float p = fminf(fmaxf(pr[8], EPSV), 1.0f - EPSV);
            bceS   += -(t8 * __logf(p) + (1.0f - t8) * __logf(1.0f - p));
            nvS    += mask;
            q45[0] = make_float2(a4, a5);
            s45f[tid] = q45[0];
        }
        __syncthreads();       // buf0 fully consumed -> free

        if (segn < NSEG) {     // refill buf0 with next segment's tile0
            const float4* p4 = reinterpret_cast<const float4*>(preds + ((size_t)segn * SEG) * 9);
            const float4* t4 = reinterpret_cast<const float4*>(tgts  + ((size_t)segn * SEG) * 9);
            float4* spd = reinterpret_cast<float4*>(&sp[0][0]);
            float4* std_ = reinterpret_cast<float4*>(&st[0][0]);
            for (int i = tid; i < NF4T; i += TPB) {
                cp16(&spd[i], &p4[i]);
                cp16(&std_[i], &t4[i]);
            }
            CP_COMMIT();
        }

        // ======== TILE 1 ========
        if (segn < NSEG) { CP_WAIT(1); } else { CP_WAIT(0); }
        __syncthreads();       // buf1 data visible
        {
            const float* pr = &sp[1][tid * 9];
            const float* tr = &st[1][tid * 9];
            float t8   = tr[8];
            float mask = (t8 > 0.5f) ? 1.0f : 0.0f;
            v1 = (t8 > 0.5f) ? 1u : 0u;

            float a4 = pr[4], a5 = pr[5];
            coordS += (fabsf(pr[0] - tr[0]) + fabsf(pr[1] - tr[1]) + fabsf(pr[2] - tr[2])
                     + fabsf(pr[3] - tr[3]) + fabsf(a4 - tr[4]) + fabsf(a5 - tr[5])) * mask;
            widthS += (fabsf(pr[6] - tr[6]) + fabsf(pr[7] - tr[7])) * mask;
            float p = fminf(fmaxf(pr[8], EPSV), 1.0f - EPSV);
            bceS   += -(t8 * __logf(p) + (1.0f - t8) * __logf(1.0f - p));
            nvS    += mask;
            q45[1] = make_float2(a4, a5);
            s45f[TILE + tid] = q45[1];
        }
        {
            unsigned b0 = __ballot_sync(0xffffffffu, v0 != 0u);
            unsigned b1 = __ballot_sync(0xffffffffu, v1 != 0u);
            if (lane == 0) { smask[wid] = b0; smask[8 + wid] = b1; }
        }
        __syncthreads();       // buf1 free; smask + s45f visible

        if (segn < NSEG) {     // refill buf1 with next segment's tile1
            const float4* p4 = reinterpret_cast<const float4*>(preds + ((size_t)segn * SEG + TILE) * 9);
            const float4* t4 = reinterpret_cast<const float4*>(tgts  + ((size_t)segn * SEG + TILE) * 9);
            float4* spd = reinterpret_cast<float4*>(&sp[1][0]);
            float4* std_ = reinterpret_cast<float4*>(&st[1][0]);
            for (int i = tid; i < NF4T; i += TPB) {
                cp16(&spd[i], &p4[i]);
                cp16(&std_[i], &t4[i]);
            }
            CP_COMMIT();
        }

        // ---- continuity of this segment (runs under both prefetches) ----
        const int rs = seg;
#pragma unroll
        for (int t = 0; t < 2; t++) {
            unsigned vv = t ? v1 : v0;
            if (vv) {
                const int j = t * TILE + tid;
                const int k = j >> 5;
                unsigned rem = (lane < 31) ? (smask[k] & (0xFFFFFFFEu << lane)) : 0u;
                int k2 = k;
                while (rem == 0u && ++k2 < 16) rem = smask[k2];
                float2 a = q45[t];
                if (rem != 0u) {
                    int nxt = (k2 << 5) + __ffs(rem) - 1;
                    float2 nb = s45f[nxt];
                    contS += 0.5f * (fabsf(a.x - nb.x) + fabsf(a.y - nb.y));
                } else {
                    g_last_p45[rs] = a;          // unique last valid in segment
                }
            }
        }
        if (tid == 0) {
            int f = SEG;
#pragma unroll
            for (int k = 15; k >= 0; k--)
                if (smask[k]) f = (k << 5) + __ffs(smask[k]) - 1;
            g_first_idx[rs] = f;
            if (f < SEG) g_first_p45[rs] = s45f[f];
        }

        seg = segn;
        // next iteration's CP_WAIT+sync orders these s45f/smask reads
        // before the next segment's writes.
    }

    // ---- block reduce + global atomic accumulate ----
    float vals[6] = {coordS, widthS, bceS, nvS, contS, reconS};
#pragma unroll
    for (int q = 0; q < 6; q++) {
        float v = warpReduceSumF(vals[q]);
        if (lane == 0) swred[q][wid] = v;
    }
    __syncthreads();
    if (wid == 0 && lane < 6) {
        float v = 0.f;
#pragma unroll
        for (int j = 0; j < 8; j++) v += swred[lane][j];
        atomicAdd(&g_acc[lane], v);
    }
    __syncthreads();

    // ---- last-block finalize ----
    if (tid == 0) {
        __threadfence();   // release: publishes this block's writes (cumulative)
        unsigned int t = atomicAdd(&g_ticket, 1u);
        slast = (t == (unsigned int)(NBLOCKS - 1)) ? 1 : 0;
    }
    __syncthreads();
    if (!slast) return;
    __threadfence();       // acquire (single block)

    // cross-segment continuity fixup: one row per thread, prefetched loads
    float fix = 0.f;
    for (int r = tid; r < B; r += TPB) {
        int    fidx[SEGS];
        float2 fp[SEGS], lp[SEGS];
#pragma unroll
        for (int s = 0; s < SEGS; s++) {
            int q = r * SEGS + s;
            fidx[s] = g_first_idx[q];
            fp[s]   = g_first_p45[q];
            lp[s]   = g_last_p45[q];
        }
        float2 nf = make_float2(0.f, 0.f);
        bool have = false;
#pragma unroll
        for (int s = SEGS - 1; s >= 0; s--) {
            if (fidx[s] < SEG) {
                if (have) fix += 0.5f * (fabsf(lp[s].x - nf.x) + fabsf(lp[s].y - nf.y));
                nf = fp[s];
                have = true;
            }
        }
    }
    {
        float v = warpReduceSumF(fix);
        if (lane == 0) swred[0][wid] = v;
    }
    __syncthreads();
    if (tid == 0) {
        float fsum = 0.f;
#pragma unroll
        for (int j = 0; j < 8; j++) fsum += swred[0][j];

        double t0 = (double)g_acc[0], t1 = (double)g_acc[1], t2 = (double)g_acc[2];
        double nv = (double)g_acc[3];
        double t4 = (double)g_acc[4] + (double)fsum;
        double t5 = (double)g_acc[5];

        double coord    = (nv > 0.0) ? t0 / fmax(nv * 6.0, 1.0) : 0.0;
        double width    = (nv > 0.0) ? t1 / fmax(nv * 2.0, 1.0) : 0.0;
        double validity = t2 / ((double)B * (double)M_ROW);
        double cont     = t4 / (double)B;
        double recon    = t5 / (double)nrec;
        out[0] = (float)(coord + width + 2.0 * validity + 0.2 * cont + 0.1 * recon);

        // self-reset for the next graph replay
        g_ticket = 0u;
        g_work   = 0u;
#pragma unroll
        for (int q = 0; q < 6; q++) g_acc[q] = 0.f;
        __threadfence();
    }
}

extern "C" void kernel_launch(void* const* d_in, const int* in_sizes, int n_in,
                              void* d_out, int out_size)
{
    const float* preds = (const float*)d_in[0];
    const float* tgts  = (const float*)d_in[1];
    const float* rec   = (const float*)d_in[2];
    const float* img   = (const float*)d_in[3];

    const int B    = in_sizes[0] / (M_ROW * 9);
    const int nrec = in_sizes[2];

    loss_fused_kernel<<<NBLOCKS, TPB>>>(preds, tgts, rec, img,
                                        (float*)d_out, B, nrec);
}

// round 13
// speedup vs baseline: 1.0102x; 1.0102x over previous
#include <cuda_runtime.h>
#include <cstdint>

// ImprovedVectorizationLoss: fused masked-L1 + BCE + continuity + recon-MSE.
// Persistent work-stealing kernel (740 blocks, 5/SM). Record tiles stream via
// cp.async.bulk (TMA path, mbarrier complete_tx) in a 2-buffer ring; recon MSE
// streams via LDG interleaved per tile phase (independent request pool).

#define M_ROW 4096
#define TPB   256
#define SEGS  8
#define SEG   (M_ROW / SEGS)         // 512
#define TILE  256
#define TILE_BYTES (TILE * 9 * 4)    // 9216 B per tensor per tile
#define NBLOCKS 740                  // 5 blocks/SM x 148 SMs
#define BMAX  512
#define EPSV  1e-7f

__device__ float        g_acc[6];
__device__ unsigned int g_ticket;
__device__ unsigned int g_work;
__device__ int          g_first_idx[BMAX * SEGS];
__device__ float2       g_first_p45[BMAX * SEGS];
__device__ float2       g_last_p45[BMAX * SEGS];

__device__ __forceinline__ float warpReduceSumF(float v) {
#pragma unroll
    for (int o = 16; o > 0; o >>= 1) v += __shfl_down_sync(0xffffffffu, v, o);
    return v;
}

__device__ __forceinline__ unsigned s2u(const void* p) {
    return (unsigned)__cvta_generic_to_shared(p);
}
__device__ __forceinline__ void mbar_init(unsigned mbar, unsigned cnt) {
    asm volatile("mbarrier.init.shared.b64 [%0], %1;" :: "r"(mbar), "r"(cnt) : "memory");
}
__device__ __forceinline__ void mbar_arrive_expect_tx(unsigned mbar, unsigned tx) {
    asm volatile("mbarrier.arrive.expect_tx.shared.b64 _, [%0], %1;" :: "r"(mbar), "r"(tx) : "memory");
}
__device__ __forceinline__ void mbar_wait(unsigned mbar, unsigned parity) {
    asm volatile(
        "{\n\t.reg .pred p;\n\t"
        "WAITLOOP_%=:\n\t"
        "mbarrier.try_wait.parity.acquire.cta.shared::cta.b64 p, [%0], %1, 0x989680;\n\t"
        "@!p bra WAITLOOP_%=;\n\t}"
        :: "r"(mbar), "r"(parity) : "memory");
}
__device__ __forceinline__ void bulk_g2s(unsigned sdst, const void* gsrc, unsigned bytes, unsigned mbar) {
    asm volatile(
        "cp.async.bulk.shared::cta.global.mbarrier::complete_tx::bytes [%0], [%1], %2, [%3];"
        :: "r"(sdst), "l"(gsrc), "r"(bytes), "r"(mbar) : "memory");
}

__global__ __launch_bounds__(TPB, 5) void loss_fused_kernel(
    const float* __restrict__ preds, const float* __restrict__ tgts,
    const float* __restrict__ rec,   const float* __restrict__ img,
    float* __restrict__ out, int B, int nrec)
{
    __shared__ __align__(128) float sp[2][TILE * 9];   // 18 KB
    __shared__ __align__(128) float st[2][TILE * 9];   // 18 KB
    __shared__ float2   s45f[SEG];                     // 4 KB
    __shared__ unsigned smask[16];
    __shared__ float    swred[6][8];
    __shared__ __align__(8) unsigned long long mbar[2];
    __shared__ int      s_seg;
    __shared__ int      slast;

    const int tid  = threadIdx.x;
    const int bid  = blockIdx.x;
    const int lane = tid & 31;
    const int wid  = tid >> 5;
    const int NSEG = B * SEGS;

    float coordS = 0.f, widthS = 0.f, bceS = 0.f, nvS = 0.f, contS = 0.f, reconS = 0.f;

    const unsigned mb0 = s2u(&mbar[0]);
    const unsigned mb1 = s2u(&mbar[1]);
    unsigned ph0 = 0u, ph1 = 0u;   // parity trackers

    // recon cursor (LDG path, interleaved)
    const float4* r4 = reinterpret_cast<const float4*>(rec);
    const float4* i4 = reinterpret_cast<const float4*>(img);
    const int n4 = nrec >> 2;
    int rcur = bid * TPB + tid;
    const int rstep = NBLOCKS * TPB;

    // ---- prologue: init barriers, steal first segment, arm both tiles ----
    if (tid == 0) {
        mbar_init(mb0, 1);
        mbar_init(mb1, 1);
        asm volatile("fence.proxy.async.shared::cta;" ::: "memory");
        s_seg = (int)atomicAdd(&g_work, 1u);
    }
    __syncthreads();
    int seg = s_seg;

    if (seg < NSEG && tid == 0) {
        const char* pb = reinterpret_cast<const char*>(preds) + (size_t)seg * SEG * 36;
        const char* tb = reinterpret_cast<const char*>(tgts)  + (size_t)seg * SEG * 36;
        mbar_arrive_expect_tx(mb0, 2 * TILE_BYTES);
        bulk_g2s(s2u(&sp[0][0]), pb, TILE_BYTES, mb0);
        bulk_g2s(s2u(&st[0][0]), tb, TILE_BYTES, mb0);
        mbar_arrive_expect_tx(mb1, 2 * TILE_BYTES);
        bulk_g2s(s2u(&sp[1][0]), pb + TILE_BYTES, TILE_BYTES, mb1);
        bulk_g2s(s2u(&st[1][0]), tb + TILE_BYTES, TILE_BYTES, mb1);
    }

    // two recon iterations cover the first fill
#pragma unroll
    for (int k = 0; k < 2; k++) {
        if (rcur < n4) {
            float4 r = r4[rcur], m = i4[rcur];
            float dx = r.x - m.x, dy = r.y - m.y, dz = r.z - m.z, dw = r.w - m.w;
            reconS += dx * dx + dy * dy + dz * dz + dw * dw;
            rcur += rstep;
        }
    }

    // ---- persistent segment loop (2-buffer TMA ring) ----
    while (seg < NSEG) {
        if (tid == 0) s_seg = (int)atomicAdd(&g_work, 1u);

        // ======== TILE 0 ========
        mbar_wait(mb0, ph0); ph0 ^= 1u;
        __syncthreads();                    // publishes s_seg; all see buf0
        const int segn = s_seg;

        unsigned v0, v1;
        float2   q45[2];
        {
            float4 rr, mm; bool rdo = (rcur < n4);
            if (rdo) { rr = r4[rcur]; mm = i4[rcur]; rcur += rstep; }

            const float* pr = &sp[0][tid * 9];
            const float* tr = &st[0][tid * 9];
            float t8   = tr[8];
            float mask = (t8 > 0.5f) ? 1.0f : 0.0f;
            v0 = (t8 > 0.5f) ? 1u : 0u;
            float a4 = pr[4], a5 = pr[5];
            coordS += (fabsf(pr[0] - tr[0]) + fabsf(pr[1] - tr[1]) + fabsf(pr[2] - tr[2])
                     + fabsf(pr[3] - tr[3]) + fabsf(a4 - tr[4]) + fabsf(a5 - tr[5])) * mask;
            widthS += (fabsf(pr[6] - tr[6]) + fabsf(pr[7] - tr[7])) * mask;
            float p = fminf(fmaxf(pr[8], EPSV), 1.0f - EPSV);
            bceS   += -(t8 * __logf(p) + (1.0f - t8) * __logf(1.0f - p));
            nvS    += mask;
            q45[0] = make_float2(a4, a5);
            s45f[tid] = q45[0];

            if (rdo) {
                float dx = rr.x - mm.x, dy = rr.y - mm.y, dz = rr.z - mm.z, dw = rr.w - mm.w;
                reconS += dx * dx + dy * dy + dz * dz + dw * dw;
            }
        }
        __syncthreads();                    // buf0 consumed -> free

        if (segn < NSEG && tid == 0) {      // refill buf0 with next seg tile0
            const char* pb = reinterpret_cast<const char*>(preds) + (size_t)segn * SEG * 36;
            const char* tb = reinterpret_cast<const char*>(tgts)  + (size_t)segn * SEG * 36;
            mbar_arrive_expect_tx(mb0, 2 * TILE_BYTES);
            bulk_g2s(s2u(&sp[0][0]), pb, TILE_BYTES, mb0);
            bulk_g2s(s2u(&st[0][0]), tb, TILE_BYTES, mb0);
        }

        // ======== TILE 1 ========
        mbar_wait(mb1, ph1); ph1 ^= 1u;
        __syncthreads();
        {
            float4 rr, mm; bool rdo = (rcur < n4);
            if (rdo) { rr = r4[rcur]; mm = i4[rcur]; rcur += rstep; }

            const float* pr = &sp[1][tid * 9];
            const float* tr = &st[1][tid * 9];
            float t8   = tr[8];
            float mask = (t8 > 0.5f) ? 1.0f : 0.0f;
            v1 = (t8 > 0.5f) ? 1u : 0u;
            float a4 = pr[4], a5 = pr[5];
            coordS += (fabsf(pr[0] - tr[0]) + fabsf(pr[1] - tr[1]) + fabsf(pr[2] - tr[2])
                     + fabsf(pr[3] - tr[3]) + fabsf(a4 - tr[4]) + fabsf(a5 - tr[5])) * mask;
            widthS += (fabsf(pr[6] - tr[6]) + fabsf(pr[7] - tr[7])) * mask;
            float p = fminf(fmaxf(pr[8], EPSV), 1.0f - EPSV);
            bceS   += -(t8 * __logf(p) + (1.0f - t8) * __logf(1.0f - p));
            nvS    += mask;
            q45[1] = make_float2(a4, a5);
            s45f[TILE + tid] = q45[1];

            if (rdo) {
                float dx = rr.x - mm.x, dy = rr.y - mm.y, dz = rr.z - mm.z, dw = rr.w - mm.w;
                reconS += dx * dx + dy * dy + dz * dz + dw * dw;
            }
        }
        {
            unsigned b0 = __ballot_sync(0xffffffffu, v0 != 0u);
            unsigned b1 = __ballot_sync(0xffffffffu, v1 != 0u);
            if (lane == 0) { smask[wid] = b0; smask[8 + wid] = b1; }
        }
        __syncthreads();                    // buf1 consumed; smask/s45f visible

        if (segn < NSEG && tid == 0) {      // refill buf1 with next seg tile1
            const char* pb = reinterpret_cast<const char*>(preds) + (size_t)segn * SEG * 36;
            const char* tb = reinterpret_cast<const char*>(tgts)  + (size_t)segn * SEG * 36;
            mbar_arrive_expect_tx(mb1, 2 * TILE_BYTES);
            bulk_g2s(s2u(&sp[1][0]), pb + TILE_BYTES, TILE_BYTES, mb1);
            bulk_g2s(s2u(&st[1][0]), tb + TILE_BYTES, TILE_BYTES, mb1);
        }

        // ---- continuity of this segment (under the refills) ----
        const int rs = seg;
#pragma unroll
        for (int t = 0; t < 2; t++) {
            unsigned vv = t ? v1 : v0;
            if (vv) {
                const int j = t * TILE + tid;
                const int k = j >> 5;
                unsigned rem = (lane < 31) ? (smask[k] & (0xFFFFFFFEu << lane)) : 0u;
                int k2 = k;
                while (rem == 0u && ++k2 < 16) rem = smask[k2];
                float2 a = q45[t];
                if (rem != 0u) {
                    int nxt = (k2 << 5) + __ffs(rem) - 1;
                    float2 nb = s45f[nxt];
                    contS += 0.5f * (fabsf(a.x - nb.x) + fabsf(a.y - nb.y));
                } else {
                    g_last_p45[rs] = a;
                }
            }
        }
        if (tid == 0) {
            int f = SEG;
#pragma unroll
            for (int k = 15; k >= 0; k--)
                if (smask[k]) f = (k << 5) + __ffs(smask[k]) - 1;
            g_first_idx[rs] = f;
            if (f < SEG) g_first_p45[rs] = s45f[f];
        }

        seg = segn;
    }

    // ---- drain remaining recon iterations ----
    for (; rcur < n4; rcur += rstep) {
        float4 r = r4[rcur], m = i4[rcur];
        float dx = r.x - m.x, dy = r.y - m.y, dz = r.z - m.z, dw = r.w - m.w;
        reconS += dx * dx + dy * dy + dz * dz + dw * dw;
    }

    // ---- block reduce + global atomics ----
    float vals[6] = {coordS, widthS, bceS, nvS, contS, reconS};
#pragma unroll
    for (int q = 0; q < 6; q++) {
        float v = warpReduceSumF(vals[q]);
        if (lane == 0) swred[q][wid] = v;
    }
    __syncthreads();
    if (wid == 0 && lane < 6) {
        float v = 0.f;
#pragma unroll
        for (int j = 0; j < 8; j++) v += swred[lane][j];
        atomicAdd(&g_acc[lane], v);
    }
    __syncthreads();

    // ---- last-block finalize ----
    if (tid == 0) {
        __threadfence();
        unsigned int t = atomicAdd(&g_ticket, 1u);
        slast = (t == (unsigned int)(NBLOCKS - 1)) ? 1 : 0;
    }
    __syncthreads();
    if (!slast) return;
    __threadfence();

    float fix = 0.f;
    for (int r = tid; r < B; r += TPB) {
        int    fidx[SEGS];
        float2 fp[SEGS], lp[SEGS];
#pragma unroll
        for (int s = 0; s < SEGS; s++) {
            int q = r * SEGS + s;
            fidx[s] = g_first_idx[q];
            fp[s]   = g_first_p45[q];
            lp[s]   = g_last_p45[q];
        }
        float2 nf = make_float2(0.f, 0.f);
        bool have = false;
#pragma unroll
        for (int s = SEGS - 1; s >= 0; s--) {
            if (fidx[s] < SEG) {
                if (have) fix += 0.5f * (fabsf(lp[s].x - nf.x) + fabsf(lp[s].y - nf.y));
                nf = fp[s];
                have = true;
            }
        }
    }
    {
        float v = warpReduceSumF(fix);
        if (lane == 0) swred[0][wid] = v;
    }
    __syncthreads();
    if (tid == 0) {
        float fsum = 0.f;
#pragma unroll
        for (int j = 0; j < 8; j++) fsum += swred[0][j];

        double t0 = (double)g_acc[0], t1 = (double)g_acc[1], t2 = (double)g_acc[2];
        double nv = (double)g_acc[3];
        double t4 = (double)g_acc[4] + (double)fsum;
        double t5 = (double)g_acc[5];

        double coord    = (nv > 0.0) ? t0 / fmax(nv * 6.0, 1.0) : 0.0;
        double width    = (nv > 0.0) ? t1 / fmax(nv * 2.0, 1.0) : 0.0;
        double validity = t2 / ((double)B * (double)M_ROW);
        double cont     = t4 / (double)B;
        double recon    = t5 / (double)nrec;
        out[0] = (float)(coord + width + 2.0 * validity + 0.2 * cont + 0.1 * recon);

        g_ticket = 0u;
        g_work   = 0u;
#pragma unroll
        for (int q = 0; q < 6; q++) g_acc[q] = 0.f;
        __threadfence();
    }
}

extern "C" void kernel_launch(void* const* d_in, const int* in_sizes, int n_in,
                              void* d_out, int out_size)
{
    const float* preds = (const float*)d_in[0];
    const float* tgts  = (const float*)d_in[1];
    const float* rec   = (const float*)d_in[2];
    const float* img   = (const float*)d_in[3];

    const int B    = in_sizes[0] / (M_ROW * 9);
    const int nrec = in_sizes[2];

    loss_fused_kernel<<<NBLOCKS, TPB>>>(preds, tgts, rec, img,
                                        (float*)d_out, B, nrec);
}